// round 4
// baseline (speedup 1.0000x reference)
#include <cuda_runtime.h>

// x: (16, 256, 128, 128) fp32, c = comp*64 + c4 (comp outer)
// out: (16, 256, 64, 64) fp32
// For each (b, c4, h2, w2): amp2[p] = sum_comp x[b, comp*64+c4, 2h2+kh, 2w2+kw]^2,
// p = kh*2+kw; first argmax p (strict >); emit the 4 component values at p.
//
// Each thread: one (b, c4, h2) and a quad of w2 outputs (4 pixels) -> per
// component: 2x LDG.128 on row 2h2, 2x on row 2h2+1 (16 loads total), one
// STG.128 per component (4 stores). Half-warp spans a full 512B input row.

#define NB   16
#define NC4  64
#define HH   128
#define WW   128
#define H2   64
#define W2   64

__device__ __forceinline__ float pick2x2(const float4& t, const float4& bt, int idx, bool hi) {
    float c0 = hi ? t.z  : t.x;
    float c1 = hi ? t.w  : t.y;
    float c2 = hi ? bt.z : bt.x;
    float c3 = hi ? bt.w : bt.y;
    float v = c0;
    v = (idx == 1) ? c1 : v;
    v = (idx == 2) ? c2 : v;
    v = (idx == 3) ? c3 : v;
    return v;
}

__global__ __launch_bounds__(256)
void qmap_kernel(const float* __restrict__ x, float* __restrict__ out) {
    int tid = blockIdx.x * blockDim.x + threadIdx.x;
    // total threads = 16 * 64 * 64 * 16 = 1,048,576
    int j   = tid & 15;           // w2 quad: w2 = 4j..4j+3 ; input w base = 8j
    int h2  = (tid >> 4)  & 63;
    int c4i = (tid >> 10) & 63;
    int b   = tid >> 16;

    const size_t plane       = (size_t)HH * WW;          // 16384
    const size_t comp_stride = (size_t)NC4 * plane;      // 64*16384

    size_t base = (size_t)(b * 4) * comp_stride
                + (size_t)c4i * plane
                + (size_t)(2 * h2) * WW
                + (size_t)(8 * j);

    // 16 independent 16B loads, front-batched
    float4 t0a[4], t0b[4], t1a[4], t1b[4];
#pragma unroll
    for (int cm = 0; cm < 4; cm++) {
        const float* p = x + base + (size_t)cm * comp_stride;
        t0a[cm] = *reinterpret_cast<const float4*>(p);
        t0b[cm] = *reinterpret_cast<const float4*>(p + 4);
        t1a[cm] = *reinterpret_cast<const float4*>(p + WW);
        t1b[cm] = *reinterpret_cast<const float4*>(p + WW + 4);
    }

    // amp^2 for the 4 pixels:
    //  k=0: t0a.xy/t1a.xy   k=1: t0a.zw/t1a.zw
    //  k=2: t0b.xy/t1b.xy   k=3: t0b.zw/t1b.zw
    float a0[4] = {0.f,0.f,0.f,0.f};
    float a1[4] = {0.f,0.f,0.f,0.f};
    float a2[4] = {0.f,0.f,0.f,0.f};
    float a3[4] = {0.f,0.f,0.f,0.f};
#pragma unroll
    for (int cm = 0; cm < 4; cm++) {
        a0[0] = fmaf(t0a[cm].x, t0a[cm].x, a0[0]);
        a0[1] = fmaf(t0a[cm].y, t0a[cm].y, a0[1]);
        a0[2] = fmaf(t1a[cm].x, t1a[cm].x, a0[2]);
        a0[3] = fmaf(t1a[cm].y, t1a[cm].y, a0[3]);
        a1[0] = fmaf(t0a[cm].z, t0a[cm].z, a1[0]);
        a1[1] = fmaf(t0a[cm].w, t0a[cm].w, a1[1]);
        a1[2] = fmaf(t1a[cm].z, t1a[cm].z, a1[2]);
        a1[3] = fmaf(t1a[cm].w, t1a[cm].w, a1[3]);
        a2[0] = fmaf(t0b[cm].x, t0b[cm].x, a2[0]);
        a2[1] = fmaf(t0b[cm].y, t0b[cm].y, a2[1]);
        a2[2] = fmaf(t1b[cm].x, t1b[cm].x, a2[2]);
        a2[3] = fmaf(t1b[cm].y, t1b[cm].y, a2[3]);
        a3[0] = fmaf(t0b[cm].z, t0b[cm].z, a3[0]);
        a3[1] = fmaf(t0b[cm].w, t0b[cm].w, a3[1]);
        a3[2] = fmaf(t1b[cm].z, t1b[cm].z, a3[2]);
        a3[3] = fmaf(t1b[cm].w, t1b[cm].w, a3[3]);
    }

    // first-argmax (strict >) per pixel
    int i0 = 0, i1 = 0, i2 = 0, i3 = 0;
    {
        float m = a0[0];
        if (a0[1] > m) { m = a0[1]; i0 = 1; }
        if (a0[2] > m) { m = a0[2]; i0 = 2; }
        if (a0[3] > m) {            i0 = 3; }
    }
    {
        float m = a1[0];
        if (a1[1] > m) { m = a1[1]; i1 = 1; }
        if (a1[2] > m) { m = a1[2]; i1 = 2; }
        if (a1[3] > m) {            i1 = 3; }
    }
    {
        float m = a2[0];
        if (a2[1] > m) { m = a2[1]; i2 = 1; }
        if (a2[2] > m) { m = a2[2]; i2 = 2; }
        if (a2[3] > m) {            i2 = 3; }
    }
    {
        float m = a3[0];
        if (a3[1] > m) { m = a3[1]; i3 = 1; }
        if (a3[2] > m) { m = a3[2]; i3 = 2; }
        if (a3[3] > m) {            i3 = 3; }
    }

    const size_t oplane       = (size_t)H2 * W2;         // 4096
    const size_t ocomp_stride = (size_t)NC4 * oplane;    // 64*4096
    size_t obase = (size_t)(b * 4) * ocomp_stride
                 + (size_t)c4i * oplane
                 + (size_t)h2 * W2
                 + (size_t)(4 * j);

#pragma unroll
    for (int cm = 0; cm < 4; cm++) {
        float4 o;
        o.x = pick2x2(t0a[cm], t1a[cm], i0, false);
        o.y = pick2x2(t0a[cm], t1a[cm], i1, true);
        o.z = pick2x2(t0b[cm], t1b[cm], i2, false);
        o.w = pick2x2(t0b[cm], t1b[cm], i3, true);
        __stcs(reinterpret_cast<float4*>(out + obase + (size_t)cm * ocomp_stride), o);
    }
}

extern "C" void kernel_launch(void* const* d_in, const int* in_sizes, int n_in,
                              void* d_out, int out_size) {
    const float* x = (const float*)d_in[0];
    float* out = (float*)d_out;
    const int total = NB * NC4 * H2 * (W2 / 4);   // 1,048,576 threads
    const int block = 256;
    const int grid  = total / block;              // 4096
    qmap_kernel<<<grid, block>>>(x, out);
}

// round 6
// speedup vs baseline: 1.0303x; 1.0303x over previous
#include <cuda_runtime.h>

// x: (16, 256, 128, 128) fp32, c = comp*64 + c4 (comp outer)
// out: (16, 256, 64, 64) fp32
// For each (b, c4, h2, w2): amp2[p] = sum_comp x[b, comp*64+c4, 2h2+kh, 2w2+kw]^2,
// p = kh*2+kw; first argmax p (strict >); emit the 4 component values at p.
//
// Winning shape (R1/R3): 2 output pixels per thread, 8 front-batched LDG.128
// (warp spans a full 512B input row), float2 stores (warp spans 256B output
// row per component). This round: cap regs via launch_bounds to lift the
// occupancy ceiling 4 -> 6 CTAs/SM.

#define NB   16
#define NC4  64
#define HH   128
#define WW   128
#define H2   64
#define W2   64

__device__ __forceinline__ float pick2x2(const float4& t, const float4& bt, int idx, bool hi) {
    float c0 = hi ? t.z  : t.x;
    float c1 = hi ? t.w  : t.y;
    float c2 = hi ? bt.z : bt.x;
    float c3 = hi ? bt.w : bt.y;
    float v = c0;
    v = (idx == 1) ? c1 : v;
    v = (idx == 2) ? c2 : v;
    v = (idx == 3) ? c3 : v;
    return v;
}

__global__ __launch_bounds__(256, 6)
void qmap_kernel(const float* __restrict__ x, float* __restrict__ out) {
    int tid = blockIdx.x * blockDim.x + threadIdx.x;
    // total threads = 16 * 64 * 64 * 32 = 2,097,152
    int j   = tid & 31;           // w2-pair: w2 = 2j, 2j+1; input w base = 4j
    int h2  = (tid >> 5)  & 63;
    int c4i = (tid >> 11) & 63;
    int b   = tid >> 17;

    const size_t plane       = (size_t)HH * WW;          // 16384
    const size_t comp_stride = (size_t)NC4 * plane;      // 64*16384

    size_t base = (size_t)(b * 4) * comp_stride
                + (size_t)c4i * plane
                + (size_t)(2 * h2) * WW
                + (size_t)(4 * j);

    // 8 independent 16B loads, front-batched
    float4 r0[4], r1[4];
#pragma unroll
    for (int cm = 0; cm < 4; cm++) {
        const float* p = x + base + (size_t)cm * comp_stride;
        r0[cm] = *reinterpret_cast<const float4*>(p);
        r1[cm] = *reinterpret_cast<const float4*>(p + WW);
    }

    // amp^2 for pixel lo (r0.xy, r1.xy) and pixel hi (r0.zw, r1.zw)
    float aA[4] = {0.f, 0.f, 0.f, 0.f};
    float aB[4] = {0.f, 0.f, 0.f, 0.f};
#pragma unroll
    for (int cm = 0; cm < 4; cm++) {
        aA[0] = fmaf(r0[cm].x, r0[cm].x, aA[0]);
        aA[1] = fmaf(r0[cm].y, r0[cm].y, aA[1]);
        aA[2] = fmaf(r1[cm].x, r1[cm].x, aA[2]);
        aA[3] = fmaf(r1[cm].y, r1[cm].y, aA[3]);
        aB[0] = fmaf(r0[cm].z, r0[cm].z, aB[0]);
        aB[1] = fmaf(r0[cm].w, r0[cm].w, aB[1]);
        aB[2] = fmaf(r1[cm].z, r1[cm].z, aB[2]);
        aB[3] = fmaf(r1[cm].w, r1[cm].w, aB[3]);
    }

    int iA = 0, iB = 0;
    {
        float m = aA[0];
        if (aA[1] > m) { m = aA[1]; iA = 1; }
        if (aA[2] > m) { m = aA[2]; iA = 2; }
        if (aA[3] > m) {            iA = 3; }
    }
    {
        float m = aB[0];
        if (aB[1] > m) { m = aB[1]; iB = 1; }
        if (aB[2] > m) { m = aB[2]; iB = 2; }
        if (aB[3] > m) {            iB = 3; }
    }

    const size_t oplane       = (size_t)H2 * W2;         // 4096
    const size_t ocomp_stride = (size_t)NC4 * oplane;    // 64*4096
    size_t obase = (size_t)(b * 4) * ocomp_stride
                 + (size_t)c4i * oplane
                 + (size_t)h2 * W2
                 + (size_t)(2 * j);

#pragma unroll
    for (int cm = 0; cm < 4; cm++) {
        float vA = pick2x2(r0[cm], r1[cm], iA, false);
        float vB = pick2x2(r0[cm], r1[cm], iB, true);
        __stcs(reinterpret_cast<float2*>(out + obase + (size_t)cm * ocomp_stride),
               make_float2(vA, vB));
    }
}

extern "C" void kernel_launch(void* const* d_in, const int* in_sizes, int n_in,
                              void* d_out, int out_size) {
    const float* x = (const float*)d_in[0];
    float* out = (float*)d_out;
    const int total = NB * NC4 * H2 * (W2 / 2);   // 2,097,152 threads
    const int block = 256;
    const int grid  = total / block;              // 8192
    qmap_kernel<<<grid, block>>>(x, out);
}